// round 2
// baseline (speedup 1.0000x reference)
#include <cuda_runtime.h>

#define KCODES 256
#define DIM 32
#define TPB 128          // threads per block
#define NBLOCKS 304      // 2 blocks per SM on 152-SM GB300, all co-resident

// Full codebook mirrored into constant memory; main loop reads dims 16..31 from
// here (warp-uniform index -> LDC on the constant port, off the L1 data path).
__constant__ float cb_const[KCODES * DIM];

__global__ void vq_zero_counts(float* counts) {
    counts[threadIdx.x] = 0.0f;
}

// ---- packed f32x2 helpers (each lane rounds as an independent IEEE fp32 op) ----
__device__ __forceinline__ unsigned long long pack2(float lo, float hi) {
    unsigned long long r;
    asm("mov.b64 %0, {%1, %2};" : "=l"(r) : "f"(lo), "f"(hi));
    return r;
}
__device__ __forceinline__ void unpack2(unsigned long long v, float& lo, float& hi) {
    asm("mov.b64 {%0, %1}, %2;" : "=f"(lo), "=f"(hi) : "l"(v));
}
__device__ __forceinline__ void fma2(unsigned long long& acc, unsigned long long a,
                                     unsigned long long b) {
    asm("fma.rn.f32x2 %0, %1, %2, %0;" : "+l"(acc) : "l"(a), "l"(b));
}

__global__ __launch_bounds__(TPB, 2) void vq_main(
    const float* __restrict__ x,
    const float* __restrict__ cb,
    float* __restrict__ out_rot,
    float* __restrict__ out_idx,
    float* __restrict__ out_counts,
    int nQuads)
{
    __shared__ __align__(16) float cb_s[KCODES * DIM];   // full codebook: 32 KB
    __shared__ float c2_s[KCODES];
    __shared__ float hist[KCODES];

    const int tid = threadIdx.x;

    // --- Stage codebook into shared; compute c2 exactly (rounded squares, sequential sum) ---
    for (int k = tid; k < KCODES; k += TPB) {
        const float4* src = reinterpret_cast<const float4*>(cb + k * DIM);
        float4* dst = reinterpret_cast<float4*>(cb_s + k * DIM);
        float row[DIM];
        #pragma unroll
        for (int j = 0; j < 8; j++) {
            float4 v = src[j];
            dst[j] = v;
            row[4*j+0] = v.x; row[4*j+1] = v.y; row[4*j+2] = v.z; row[4*j+3] = v.w;
        }
        float s = 0.0f;
        #pragma unroll
        for (int d = 0; d < DIM; d++)
            s = __fadd_rn(s, __fmul_rn(row[d], row[d]));
        c2_s[k] = s;
        hist[k] = 0.0f;
    }
    __syncthreads();

    // Balanced contiguous quad (4-token group) ranges per block.
    const long long qs = (long long)blockIdx.x * nQuads / NBLOCKS;
    const long long qe = (long long)(blockIdx.x + 1) * nQuads / NBLOCKS;

    for (long long q = qs + tid; q < qe; q += TPB) {
        const float* xb = x + q * (4LL * DIM);

        // Load 4 tokens; pack (t0,t1) and (t2,t3) per dim. x2 chains stay
        // scalar sequential in ascending d (reference order).
        unsigned long long xp01[DIM], xp23[DIM];
        float x2v[4] = {0.f, 0.f, 0.f, 0.f};
        #pragma unroll
        for (int j = 0; j < 8; j++) {
            float4 a = reinterpret_cast<const float4*>(xb          )[j];
            float4 b = reinterpret_cast<const float4*>(xb +   DIM  )[j];
            float4 c = reinterpret_cast<const float4*>(xb + 2*DIM  )[j];
            float4 d = reinterpret_cast<const float4*>(xb + 3*DIM  )[j];
            xp01[4*j+0] = pack2(a.x, b.x); xp23[4*j+0] = pack2(c.x, d.x);
            xp01[4*j+1] = pack2(a.y, b.y); xp23[4*j+1] = pack2(c.y, d.y);
            xp01[4*j+2] = pack2(a.z, b.z); xp23[4*j+2] = pack2(c.z, d.z);
            xp01[4*j+3] = pack2(a.w, b.w); xp23[4*j+3] = pack2(c.w, d.w);
            x2v[0] = __fadd_rn(x2v[0], __fmul_rn(a.x,a.x)); x2v[0] = __fadd_rn(x2v[0], __fmul_rn(a.y,a.y));
            x2v[0] = __fadd_rn(x2v[0], __fmul_rn(a.z,a.z)); x2v[0] = __fadd_rn(x2v[0], __fmul_rn(a.w,a.w));
            x2v[1] = __fadd_rn(x2v[1], __fmul_rn(b.x,b.x)); x2v[1] = __fadd_rn(x2v[1], __fmul_rn(b.y,b.y));
            x2v[1] = __fadd_rn(x2v[1], __fmul_rn(b.z,b.z)); x2v[1] = __fadd_rn(x2v[1], __fmul_rn(b.w,b.w));
            x2v[2] = __fadd_rn(x2v[2], __fmul_rn(c.x,c.x)); x2v[2] = __fadd_rn(x2v[2], __fmul_rn(c.y,c.y));
            x2v[2] = __fadd_rn(x2v[2], __fmul_rn(c.z,c.z)); x2v[2] = __fadd_rn(x2v[2], __fmul_rn(c.w,c.w));
            x2v[3] = __fadd_rn(x2v[3], __fmul_rn(d.x,d.x)); x2v[3] = __fadd_rn(x2v[3], __fmul_rn(d.y,d.y));
            x2v[3] = __fadd_rn(x2v[3], __fmul_rn(d.z,d.z)); x2v[3] = __fadd_rn(x2v[3], __fmul_rn(d.w,d.w));
        }

        float best[4] = {3.4e38f, 3.4e38f, 3.4e38f, 3.4e38f};
        int   bi[4]   = {0, 0, 0, 0};

        // --- Argmin scan, 2 codes per iteration, dims split shared/const ---
        #pragma unroll 1
        for (int k = 0; k < KCODES; k += 2) {
            unsigned long long a01 = 0ull, a23 = 0ull;   // code k   accumulators
            unsigned long long b01 = 0ull, b23 = 0ull;   // code k+1 accumulators

            // dims 0..15 from shared (4 LDS.128 per code)
            #pragma unroll
            for (int jj = 0; jj < 4; jj++) {
                float4 ca = reinterpret_cast<const float4*>(cb_s +  k      * DIM)[jj];
                float4 cc = reinterpret_cast<const float4*>(cb_s + (k + 1) * DIM)[jj];
                const int d = 4 * jj;
                unsigned long long t;
                t = pack2(ca.x, ca.x); fma2(a01, xp01[d+0], t); fma2(a23, xp23[d+0], t);
                t = pack2(ca.y, ca.y); fma2(a01, xp01[d+1], t); fma2(a23, xp23[d+1], t);
                t = pack2(ca.z, ca.z); fma2(a01, xp01[d+2], t); fma2(a23, xp23[d+2], t);
                t = pack2(ca.w, ca.w); fma2(a01, xp01[d+3], t); fma2(a23, xp23[d+3], t);
                t = pack2(cc.x, cc.x); fma2(b01, xp01[d+0], t); fma2(b23, xp23[d+0], t);
                t = pack2(cc.y, cc.y); fma2(b01, xp01[d+1], t); fma2(b23, xp23[d+1], t);
                t = pack2(cc.z, cc.z); fma2(b01, xp01[d+2], t); fma2(b23, xp23[d+2], t);
                t = pack2(cc.w, cc.w); fma2(b01, xp01[d+3], t); fma2(b23, xp23[d+3], t);
            }
            // dims 16..31 from constant memory (uniform index -> LDC, off L1)
            #pragma unroll
            for (int jj = 0; jj < 4; jj++) {
                float4 ca = reinterpret_cast<const float4*>(cb_const +  k      * DIM + 16)[jj];
                float4 cc = reinterpret_cast<const float4*>(cb_const + (k + 1) * DIM + 16)[jj];
                const int d = 16 + 4 * jj;
                unsigned long long t;
                t = pack2(ca.x, ca.x); fma2(a01, xp01[d+0], t); fma2(a23, xp23[d+0], t);
                t = pack2(ca.y, ca.y); fma2(a01, xp01[d+1], t); fma2(a23, xp23[d+1], t);
                t = pack2(ca.z, ca.z); fma2(a01, xp01[d+2], t); fma2(a23, xp23[d+2], t);
                t = pack2(ca.w, ca.w); fma2(a01, xp01[d+3], t); fma2(a23, xp23[d+3], t);
                t = pack2(cc.x, cc.x); fma2(b01, xp01[d+0], t); fma2(b23, xp23[d+0], t);
                t = pack2(cc.y, cc.y); fma2(b01, xp01[d+1], t); fma2(b23, xp23[d+1], t);
                t = pack2(cc.z, cc.z); fma2(b01, xp01[d+2], t); fma2(b23, xp23[d+2], t);
                t = pack2(cc.w, cc.w); fma2(b01, xp01[d+3], t); fma2(b23, xp23[d+3], t);
            }

            // d2 = fl(fl(x2 - 2*dot) + c2), strict <, ascending k (first-index tie-break)
            float dot[4][2];
            unpack2(a01, dot[0][0], dot[1][0]); unpack2(a23, dot[2][0], dot[3][0]);
            unpack2(b01, dot[0][1], dot[1][1]); unpack2(b23, dot[2][1], dot[3][1]);
            const float c2a = c2_s[k], c2b = c2_s[k + 1];
            #pragma unroll
            for (int t4 = 0; t4 < 4; t4++) {
                float v;
                v = __fadd_rn(__fadd_rn(x2v[t4], __fmul_rn(-2.0f, dot[t4][0])), c2a);
                if (v < best[t4]) { best[t4] = v; bi[t4] = k; }
                v = __fadd_rn(__fadd_rn(x2v[t4], __fmul_rn(-2.0f, dot[t4][1])), c2b);
                if (v < best[t4]) { best[t4] = v; bi[t4] = k + 1; }
            }
        }

        // --- Per-token epilogue: histogram + rotation-trick output ---
        #pragma unroll
        for (int t4 = 0; t4 < 4; t4++) {
            const int code = bi[t4];
            atomicAdd(&hist[code], 1.0f);

            // unpack this token's x back to scalars
            float xr[DIM];
            #pragma unroll
            for (int d = 0; d < DIM; d++) {
                float lo, hi;
                if (t4 < 2) { unpack2(xp01[d], lo, hi); }
                else        { unpack2(xp23[d], lo, hi); }
                xr[d] = (t4 & 1) ? hi : lo;
            }

            float qv[DIM];
            const float4* qrow = reinterpret_cast<const float4*>(cb_s + code * DIM);
            #pragma unroll
            for (int j = 0; j < 8; j++) {
                float4 v = qrow[j];
                qv[4*j+0] = v.x; qv[4*j+1] = v.y; qv[4*j+2] = v.z; qv[4*j+3] = v.w;
            }

            float q2 = 0.f, dotq = 0.f;
            #pragma unroll
            for (int d = 0; d < DIM; d++) {
                q2   = __fmaf_rn(qv[d], qv[d], q2);
                dotq = __fmaf_rn(xr[d], qv[d], dotq);
            }
            const float eps = 1e-6f;
            const float x2t = x2v[t4];
            float inx = 1.0f / fmaxf(sqrtf(x2t), eps);
            float inq = 1.0f / fmaxf(sqrtf(q2),  eps);
            float u2  = x2t * inx * inx;
            float qh2 = q2  * inq * inq;
            float uq  = dotq * inx * inq;
            float w2  = u2 + qh2 + 2.0f * uq;
            float iw  = 1.0f / fmaxf(sqrtf(w2), eps);
            float ew_un = x2t * inx + dotq * inq;
            float ew  = ew_un * iw;
            float eu  = x2t * inx;
            float a   = -2.0f * ew * iw;
            float s1  = 1.0f + a * inx;
            float s2  = (a + 2.0f * eu) * inq;

            float4* rp = reinterpret_cast<float4*>(out_rot + (q * 4 + t4) * DIM);
            #pragma unroll
            for (int j = 0; j < 8; j++) {
                float4 v;
                v.x = xr[4*j+0] * s1 + qv[4*j+0] * s2;
                v.y = xr[4*j+1] * s1 + qv[4*j+1] * s2;
                v.z = xr[4*j+2] * s1 + qv[4*j+2] * s2;
                v.w = xr[4*j+3] * s1 + qv[4*j+3] * s2;
                rp[j] = v;
            }
            out_idx[q * 4 + t4] = (float)code;
        }
    }

    // --- Flush block-local histogram ---
    __syncthreads();
    for (int k = tid; k < KCODES; k += TPB)
        atomicAdd(&out_counts[k], hist[k]);
}

extern "C" void kernel_launch(void* const* d_in, const int* in_sizes, int n_in,
                              void* d_out, int out_size) {
    const float* x  = (const float*)d_in[0];
    const float* cb = (const float*)d_in[1];
    float* out = (float*)d_out;

    const int N = in_sizes[0] / DIM;            // 524288
    const int nQuads = N / 4;                   // 131072
    float* rot    = out;
    float* idx    = out + (size_t)N * DIM;
    float* counts = idx + N;

    // Mirror codebook into constant memory (D2D async memcpy: graph-capturable).
    cudaMemcpyToSymbolAsync(cb_const, cb, KCODES * DIM * sizeof(float), 0,
                            cudaMemcpyDeviceToDevice, 0);
    vq_zero_counts<<<1, KCODES>>>(counts);
    vq_main<<<NBLOCKS, TPB>>>(x, cb, rot, idx, counts, nQuads);
}

// round 3
// speedup vs baseline: 1.0699x; 1.0699x over previous
#include <cuda_runtime.h>

#define KCODES 256
#define DIM 32
#define TPB 128
#define NBLOCKS 304      // 2 CTAs per SM on 152-SM GB300 -> single wave

__global__ void vq_zero_counts(float* counts) {
    counts[threadIdx.x] = 0.0f;
}

// ---- packed f32x2 helpers (each lane is an independent IEEE fp32 op) ----
__device__ __forceinline__ unsigned long long pack2(float lo, float hi) {
    unsigned long long r;
    asm("mov.b64 %0, {%1, %2};" : "=l"(r) : "f"(lo), "f"(hi));
    return r;
}
__device__ __forceinline__ void unpack2(unsigned long long v, float& lo, float& hi) {
    asm("mov.b64 {%0, %1}, %2;" : "=f"(lo), "=f"(hi) : "l"(v));
}
__device__ __forceinline__ void fma2(unsigned long long& acc, unsigned long long a,
                                     unsigned long long b) {
    asm("fma.rn.f32x2 %0, %1, %2, %0;" : "+l"(acc) : "l"(a), "l"(b));
}

__global__ __launch_bounds__(TPB, 2) void vq_main(
    const float* __restrict__ x,
    const float* __restrict__ cb,
    float* __restrict__ out_rot,
    float* __restrict__ out_idx,
    float* __restrict__ out_counts,
    int nQuads)
{
    // Codebook stored PRE-DUPLICATED: row k = (c0,c0,c1,c1,...,c31,c31) = 64 floats.
    // One LDS.128 yields two broadcast f32x2 operands with no ALU packing.
    __shared__ __align__(16) float cbd[KCODES * DIM * 2];   // 64 KB
    __shared__ float c2_s[KCODES];
    __shared__ float hist[KCODES];

    const int tid = threadIdx.x;

    // --- Stage duplicated codebook; compute c2 exactly (rounded squares, seq sum) ---
    for (int k = tid; k < KCODES; k += TPB) {
        const float4* src = reinterpret_cast<const float4*>(cb + k * DIM);
        float4* dst = reinterpret_cast<float4*>(cbd + k * (DIM * 2));
        float row[DIM];
        #pragma unroll
        for (int j = 0; j < 8; j++) {
            float4 v = src[j];
            row[4*j+0] = v.x; row[4*j+1] = v.y; row[4*j+2] = v.z; row[4*j+3] = v.w;
        }
        #pragma unroll
        for (int jj = 0; jj < 16; jj++) {
            float4 w;
            w.x = row[2*jj];     w.y = row[2*jj];
            w.z = row[2*jj + 1]; w.w = row[2*jj + 1];
            dst[jj] = w;
        }
        float s = 0.0f;
        #pragma unroll
        for (int d = 0; d < DIM; d++)
            s = __fadd_rn(s, __fmul_rn(row[d], row[d]));
        c2_s[k] = s;
        hist[k] = 0.0f;
    }
    __syncthreads();

    // Balanced contiguous quad ranges per block (single wave, no tail).
    const int qs = (int)(((long long)blockIdx.x * nQuads) / NBLOCKS);
    const int qe = (int)(((long long)(blockIdx.x + 1) * nQuads) / NBLOCKS);

    for (int q = qs + tid; q < qe; q += TPB) {
        const float* xb = x + (long long)q * (4 * DIM);

        // Load 4 tokens; pack (t0,t1) and (t2,t3) per dim (once, outside k-loop).
        unsigned long long xp01[DIM], xp23[DIM];
        float x2v[4] = {0.f, 0.f, 0.f, 0.f};
        #pragma unroll
        for (int j = 0; j < 8; j++) {
            float4 a = reinterpret_cast<const float4*>(xb          )[j];
            float4 b = reinterpret_cast<const float4*>(xb +   DIM  )[j];
            float4 c = reinterpret_cast<const float4*>(xb + 2*DIM  )[j];
            float4 d = reinterpret_cast<const float4*>(xb + 3*DIM  )[j];
            xp01[4*j+0] = pack2(a.x, b.x); xp23[4*j+0] = pack2(c.x, d.x);
            xp01[4*j+1] = pack2(a.y, b.y); xp23[4*j+1] = pack2(c.y, d.y);
            xp01[4*j+2] = pack2(a.z, b.z); xp23[4*j+2] = pack2(c.z, d.z);
            xp01[4*j+3] = pack2(a.w, b.w); xp23[4*j+3] = pack2(c.w, d.w);
            x2v[0] = __fadd_rn(x2v[0], __fmul_rn(a.x,a.x)); x2v[0] = __fadd_rn(x2v[0], __fmul_rn(a.y,a.y));
            x2v[0] = __fadd_rn(x2v[0], __fmul_rn(a.z,a.z)); x2v[0] = __fadd_rn(x2v[0], __fmul_rn(a.w,a.w));
            x2v[1] = __fadd_rn(x2v[1], __fmul_rn(b.x,b.x)); x2v[1] = __fadd_rn(x2v[1], __fmul_rn(b.y,b.y));
            x2v[1] = __fadd_rn(x2v[1], __fmul_rn(b.z,b.z)); x2v[1] = __fadd_rn(x2v[1], __fmul_rn(b.w,b.w));
            x2v[2] = __fadd_rn(x2v[2], __fmul_rn(c.x,c.x)); x2v[2] = __fadd_rn(x2v[2], __fmul_rn(c.y,c.y));
            x2v[2] = __fadd_rn(x2v[2], __fmul_rn(c.z,c.z)); x2v[2] = __fadd_rn(x2v[2], __fmul_rn(c.w,c.w));
            x2v[3] = __fadd_rn(x2v[3], __fmul_rn(d.x,d.x)); x2v[3] = __fadd_rn(x2v[3], __fmul_rn(d.y,d.y));
            x2v[3] = __fadd_rn(x2v[3], __fmul_rn(d.z,d.z)); x2v[3] = __fadd_rn(x2v[3], __fmul_rn(d.w,d.w));
        }

        float best[4] = {3.4e38f, 3.4e38f, 3.4e38f, 3.4e38f};
        int   bi[4]   = {0, 0, 0, 0};

        // --- Argmin scan: 2 codes/iter, 4 tokens, pure LDS.128 + FFMA2 ---
        #pragma unroll 1
        for (int k = 0; k < KCODES; k += 2) {
            const ulonglong2* ca = reinterpret_cast<const ulonglong2*>(cbd +  k      * (DIM * 2));
            const ulonglong2* cc = reinterpret_cast<const ulonglong2*>(cbd + (k + 1) * (DIM * 2));
            unsigned long long a01 = 0ull, a23 = 0ull;
            unsigned long long b01 = 0ull, b23 = 0ull;

            #pragma unroll
            for (int jj = 0; jj < 16; jj++) {
                ulonglong2 va = ca[jj];   // ( (c_d,c_d), (c_{d+1},c_{d+1}) )
                ulonglong2 vb = cc[jj];
                const int d = 2 * jj;
                fma2(a01, xp01[d],     va.x); fma2(a23, xp23[d],     va.x);
                fma2(a01, xp01[d + 1], va.y); fma2(a23, xp23[d + 1], va.y);
                fma2(b01, xp01[d],     vb.x); fma2(b23, xp23[d],     vb.x);
                fma2(b01, xp01[d + 1], vb.y); fma2(b23, xp23[d + 1], vb.y);
            }

            // d2 = fl(fl(x2 - 2*dot) + c2), strict <, ascending k (first-index ties)
            float dot[4][2];
            unpack2(a01, dot[0][0], dot[1][0]); unpack2(a23, dot[2][0], dot[3][0]);
            unpack2(b01, dot[0][1], dot[1][1]); unpack2(b23, dot[2][1], dot[3][1]);
            const float c2a = c2_s[k], c2b = c2_s[k + 1];
            #pragma unroll
            for (int t4 = 0; t4 < 4; t4++) {
                float v;
                v = __fadd_rn(__fadd_rn(x2v[t4], __fmul_rn(-2.0f, dot[t4][0])), c2a);
                if (v < best[t4]) { best[t4] = v; bi[t4] = k; }
                v = __fadd_rn(__fadd_rn(x2v[t4], __fmul_rn(-2.0f, dot[t4][1])), c2b);
                if (v < best[t4]) { best[t4] = v; bi[t4] = k + 1; }
            }
        }

        // --- Per-token epilogue: histogram + rotation-trick output ---
        #pragma unroll
        for (int t4 = 0; t4 < 4; t4++) {
            const int code = bi[t4];
            atomicAdd(&hist[code], 1.0f);

            float xr[DIM];
            #pragma unroll
            for (int d = 0; d < DIM; d++) {
                float lo, hi;
                if (t4 < 2) { unpack2(xp01[d], lo, hi); }
                else        { unpack2(xp23[d], lo, hi); }
                xr[d] = (t4 & 1) ? hi : lo;
            }

            // q row from global codebook (32 KB, L1-resident; divergent index ok)
            float qv[DIM];
            const float4* qrow = reinterpret_cast<const float4*>(cb + code * DIM);
            #pragma unroll
            for (int j = 0; j < 8; j++) {
                float4 v = __ldg(qrow + j);
                qv[4*j+0] = v.x; qv[4*j+1] = v.y; qv[4*j+2] = v.z; qv[4*j+3] = v.w;
            }

            float q2 = 0.f, dotq = 0.f;
            #pragma unroll
            for (int d = 0; d < DIM; d++) {
                q2   = __fmaf_rn(qv[d], qv[d], q2);
                dotq = __fmaf_rn(xr[d], qv[d], dotq);
            }
            const float eps = 1e-6f;
            const float x2t = x2v[t4];
            float inx = 1.0f / fmaxf(sqrtf(x2t), eps);
            float inq = 1.0f / fmaxf(sqrtf(q2),  eps);
            float u2  = x2t * inx * inx;
            float qh2 = q2  * inq * inq;
            float uq  = dotq * inx * inq;
            float w2  = u2 + qh2 + 2.0f * uq;
            float iw  = 1.0f / fmaxf(sqrtf(w2), eps);
            float ew_un = x2t * inx + dotq * inq;
            float ew  = ew_un * iw;
            float eu  = x2t * inx;
            float a   = -2.0f * ew * iw;
            float s1  = 1.0f + a * inx;
            float s2  = (a + 2.0f * eu) * inq;

            float4* rp = reinterpret_cast<float4*>(out_rot + ((long long)q * 4 + t4) * DIM);
            #pragma unroll
            for (int j = 0; j < 8; j++) {
                float4 v;
                v.x = xr[4*j+0] * s1 + qv[4*j+0] * s2;
                v.y = xr[4*j+1] * s1 + qv[4*j+1] * s2;
                v.z = xr[4*j+2] * s1 + qv[4*j+2] * s2;
                v.w = xr[4*j+3] * s1 + qv[4*j+3] * s2;
                rp[j] = v;
            }
            out_idx[(long long)q * 4 + t4] = (float)code;
        }
    }

    // --- Flush block-local histogram ---
    __syncthreads();
    for (int k = tid; k < KCODES; k += TPB)
        atomicAdd(&out_counts[k], hist[k]);
}

extern "C" void kernel_launch(void* const* d_in, const int* in_sizes, int n_in,
                              void* d_out, int out_size) {
    const float* x  = (const float*)d_in[0];
    const float* cb = (const float*)d_in[1];
    float* out = (float*)d_out;

    const int N = in_sizes[0] / DIM;            // 524288
    const int nQuads = N / 4;                   // 131072
    float* rot    = out;
    float* idx    = out + (size_t)N * DIM;
    float* counts = idx + N;

    vq_zero_counts<<<1, KCODES>>>(counts);
    vq_main<<<NBLOCKS, TPB>>>(x, cb, rot, idx, counts, nQuads);
}

// round 4
// speedup vs baseline: 1.5193x; 1.4201x over previous
#include <cuda_runtime.h>

#define KCODES 256
#define DIM 32
#define TPB 128
#define NBLOCKS 456      // 3 CTAs/SM on 152 SMs -> single wave

// Full codebook mirrored in constant memory; main loop reads dims 16..31 from
// here (uniform index -> constant port, off the L1/shared data path).
__constant__ float cb_c[KCODES * DIM];

__global__ void vq_zero_counts(float* counts) {
    counts[threadIdx.x] = 0.0f;
}

__global__ __launch_bounds__(TPB, 3) void vq_main(
    const float* __restrict__ x,
    const float* __restrict__ cb,
    float* __restrict__ out_rot,
    float* __restrict__ out_idx,
    float* __restrict__ out_counts,
    int nQuads)
{
    __shared__ __align__(16) float cb_lo[KCODES * 16];   // dims 0..15, 16 KB
    __shared__ float c2_s[KCODES];
    __shared__ float hist[KCODES];

    const int tid = threadIdx.x;

    // --- Stage dims 0..15 into shared; compute c2 exactly (rounded squares, seq sum) ---
    for (int k = tid; k < KCODES; k += TPB) {
        const float4* src = reinterpret_cast<const float4*>(cb + k * DIM);
        float4* dst = reinterpret_cast<float4*>(cb_lo + k * 16);
        float row[DIM];
        #pragma unroll
        for (int j = 0; j < 8; j++) {
            float4 v = src[j];
            row[4*j+0] = v.x; row[4*j+1] = v.y; row[4*j+2] = v.z; row[4*j+3] = v.w;
            if (j < 4) dst[j] = v;
        }
        float s = 0.0f;
        #pragma unroll
        for (int d = 0; d < DIM; d++)
            s = __fadd_rn(s, __fmul_rn(row[d], row[d]));
        c2_s[k] = s;
        hist[k] = 0.0f;
    }
    __syncthreads();

    // Balanced contiguous quad ranges per block.
    const int qs = (int)(((long long)blockIdx.x * nQuads) / NBLOCKS);
    const int qe = (int)(((long long)(blockIdx.x + 1) * nQuads) / NBLOCKS);

    for (int q = qs + tid; q < qe; q += TPB) {
        const float* xb = x + (long long)q * (4 * DIM);

        // Load 4 tokens into registers; x2 sequential ascending d (reference order).
        float xr[4][DIM];
        float x2v[4];
        #pragma unroll
        for (int t = 0; t < 4; t++) {
            #pragma unroll
            for (int j = 0; j < 8; j++) {
                float4 v = reinterpret_cast<const float4*>(xb + t * DIM)[j];
                xr[t][4*j+0] = v.x; xr[t][4*j+1] = v.y;
                xr[t][4*j+2] = v.z; xr[t][4*j+3] = v.w;
            }
            float s = 0.0f;
            #pragma unroll
            for (int d = 0; d < DIM; d++)
                s = __fadd_rn(s, __fmul_rn(xr[t][d], xr[t][d]));
            x2v[t] = s;
        }

        float best[4] = {3.4e38f, 3.4e38f, 3.4e38f, 3.4e38f};
        int   bi[4]   = {0, 0, 0, 0};

        // --- Argmin scan: 2 codes/iter × 4 tokens, scalar FFMA only ---
        #pragma unroll 1
        for (int k = 0; k < KCODES; k += 2) {
            float da[4] = {0.f, 0.f, 0.f, 0.f};   // dot vs code k
            float db[4] = {0.f, 0.f, 0.f, 0.f};   // dot vs code k+1

            // dims 0..15 from shared (4 LDS.128 per code)
            #pragma unroll
            for (int jj = 0; jj < 4; jj++) {
                float4 ca = reinterpret_cast<const float4*>(cb_lo +  k      * 16)[jj];
                float4 cc = reinterpret_cast<const float4*>(cb_lo + (k + 1) * 16)[jj];
                const int d = 4 * jj;
                #pragma unroll
                for (int t = 0; t < 4; t++) {
                    da[t] = __fmaf_rn(xr[t][d+0], ca.x, da[t]);
                    da[t] = __fmaf_rn(xr[t][d+1], ca.y, da[t]);
                    da[t] = __fmaf_rn(xr[t][d+2], ca.z, da[t]);
                    da[t] = __fmaf_rn(xr[t][d+3], ca.w, da[t]);
                    db[t] = __fmaf_rn(xr[t][d+0], cc.x, db[t]);
                    db[t] = __fmaf_rn(xr[t][d+1], cc.y, db[t]);
                    db[t] = __fmaf_rn(xr[t][d+2], cc.z, db[t]);
                    db[t] = __fmaf_rn(xr[t][d+3], cc.w, db[t]);
                }
            }
            // dims 16..31 from constant (uniform index -> constant port)
            #pragma unroll
            for (int jj = 0; jj < 4; jj++) {
                float4 ca = reinterpret_cast<const float4*>(cb_c +  k      * DIM + 16)[jj];
                float4 cc = reinterpret_cast<const float4*>(cb_c + (k + 1) * DIM + 16)[jj];
                const int d = 16 + 4 * jj;
                #pragma unroll
                for (int t = 0; t < 4; t++) {
                    da[t] = __fmaf_rn(xr[t][d+0], ca.x, da[t]);
                    da[t] = __fmaf_rn(xr[t][d+1], ca.y, da[t]);
                    da[t] = __fmaf_rn(xr[t][d+2], ca.z, da[t]);
                    da[t] = __fmaf_rn(xr[t][d+3], ca.w, da[t]);
                    db[t] = __fmaf_rn(xr[t][d+0], cc.x, db[t]);
                    db[t] = __fmaf_rn(xr[t][d+1], cc.y, db[t]);
                    db[t] = __fmaf_rn(xr[t][d+2], cc.z, db[t]);
                    db[t] = __fmaf_rn(xr[t][d+3], cc.w, db[t]);
                }
            }

            // d2 = fl(fl(x2 - 2*dot) + c2); strict <, ascending k = first-index ties
            const float c2a = c2_s[k], c2b = c2_s[k + 1];
            #pragma unroll
            for (int t = 0; t < 4; t++) {
                float v;
                v = __fadd_rn(__fadd_rn(x2v[t], __fmul_rn(-2.0f, da[t])), c2a);
                if (v < best[t]) { best[t] = v; bi[t] = k; }
                v = __fadd_rn(__fadd_rn(x2v[t], __fmul_rn(-2.0f, db[t])), c2b);
                if (v < best[t]) { best[t] = v; bi[t] = k + 1; }
            }
        }

        // --- Per-token epilogue: histogram + rotation-trick output ---
        #pragma unroll
        for (int t = 0; t < 4; t++) {
            const int code = bi[t];
            atomicAdd(&hist[code], 1.0f);

            float qv[DIM];
            const float4* qrow = reinterpret_cast<const float4*>(cb + code * DIM);
            #pragma unroll
            for (int j = 0; j < 8; j++) {
                float4 v = __ldg(qrow + j);
                qv[4*j+0] = v.x; qv[4*j+1] = v.y; qv[4*j+2] = v.z; qv[4*j+3] = v.w;
            }

            float q2 = 0.f, dotq = 0.f;
            #pragma unroll
            for (int d = 0; d < DIM; d++) {
                q2   = __fmaf_rn(qv[d], qv[d], q2);
                dotq = __fmaf_rn(xr[t][d], qv[d], dotq);
            }
            const float eps = 1e-6f;
            const float x2t = x2v[t];
            float inx = 1.0f / fmaxf(sqrtf(x2t), eps);
            float inq = 1.0f / fmaxf(sqrtf(q2),  eps);
            float u2  = x2t * inx * inx;
            float qh2 = q2  * inq * inq;
            float uq  = dotq * inx * inq;
            float w2  = u2 + qh2 + 2.0f * uq;
            float iw  = 1.0f / fmaxf(sqrtf(w2), eps);
            float ew_un = x2t * inx + dotq * inq;
            float ew  = ew_un * iw;
            float eu  = x2t * inx;
            float a   = -2.0f * ew * iw;
            float s1  = 1.0f + a * inx;
            float s2  = (a + 2.0f * eu) * inq;

            float4* rp = reinterpret_cast<float4*>(out_rot + ((long long)q * 4 + t) * DIM);
            #pragma unroll
            for (int j = 0; j < 8; j++) {
                float4 v;
                v.x = xr[t][4*j+0] * s1 + qv[4*j+0] * s2;
                v.y = xr[t][4*j+1] * s1 + qv[4*j+1] * s2;
                v.z = xr[t][4*j+2] * s1 + qv[4*j+2] * s2;
                v.w = xr[t][4*j+3] * s1 + qv[4*j+3] * s2;
                rp[j] = v;
            }
            out_idx[(long long)q * 4 + t] = (float)code;
        }
    }

    // --- Flush block-local histogram ---
    __syncthreads();
    for (int k = tid; k < KCODES; k += TPB)
        atomicAdd(&out_counts[k], hist[k]);
}

extern "C" void kernel_launch(void* const* d_in, const int* in_sizes, int n_in,
                              void* d_out, int out_size) {
    const float* x  = (const float*)d_in[0];
    const float* cb = (const float*)d_in[1];
    float* out = (float*)d_out;

    const int N = in_sizes[0] / DIM;            // 524288
    const int nQuads = N / 4;                   // 131072
    float* rot    = out;
    float* idx    = out + (size_t)N * DIM;
    float* counts = idx + N;

    cudaMemcpyToSymbolAsync(cb_c, cb, KCODES * DIM * sizeof(float), 0,
                            cudaMemcpyDeviceToDevice, 0);
    vq_zero_counts<<<1, KCODES>>>(counts);
    vq_main<<<NBLOCKS, TPB>>>(x, cb, rot, idx, counts, nQuads);
}